// round 6
// baseline (speedup 1.0000x reference)
#include <cuda_runtime.h>
#include <cstdint>

#define D 128
#define MAXN 100000
#define BM 128
#define BN_EPS 1e-5f

// ---------------- scratch (device globals; no runtime allocation) -----------
__device__ __align__(16) float g_agg[(size_t)MAXN * D];
__device__ __align__(16) float g_y[(size_t)MAXN * D];
__device__ float g_csrc[MAXN];
__device__ float g_cdst[MAXN];
__device__ int   g_odeg[MAXN];
__device__ int   g_ideg[MAXN];
__device__ __align__(16) float g_colsum[D];
__device__ __align__(16) float g_colsq[D];
__device__ __align__(16) float g_scale[D];
__device__ __align__(16) float g_shift[D];

// ---------------- degree histograms -----------------------------------------
__global__ void k_degrees(const int* __restrict__ src, const int* __restrict__ dst, int E) {
    int e = blockIdx.x * blockDim.x + threadIdx.x;
    if (e < E) {
        atomicAdd(&g_odeg[src[e]], 1);
        atomicAdd(&g_ideg[dst[e]], 1);
    }
}

__global__ void k_cnorm(int N) {
    int i = blockIdx.x * blockDim.x + threadIdx.x;
    if (i < N) {
        g_csrc[i] = rsqrtf(fmaxf((float)g_odeg[i], 1.0f));
        g_cdst[i] = rsqrtf(fmaxf((float)g_ideg[i], 1.0f));
    }
}

// ---------------- edge aggregation: warp per edge, v4 reduction --------------
__global__ __launch_bounds__(256) void k_aggregate(
    const float4* __restrict__ x4, const int* __restrict__ src,
    const int* __restrict__ dst, int E) {
    int t = blockIdx.x * blockDim.x + threadIdx.x;
    int e = t >> 5;
    if (e >= E) return;
    int lane = t & 31;
    int s = __ldg(&src[e]);
    int d = __ldg(&dst[e]);
    float c = g_csrc[s];
    float4 v = __ldg(&x4[(size_t)s * 32 + lane]);
    v.x *= c; v.y *= c; v.z *= c; v.w *= c;
    float* p = g_agg + ((size_t)d * D + lane * 4);
    asm volatile("red.global.add.v4.f32 [%0], {%1, %2, %3, %4};"
                 :: "l"(p), "f"(v.x), "f"(v.y), "f"(v.z), "f"(v.w) : "memory");
}

// ---------------- tf32 tensor-core single-branch GEMM ------------------------
__device__ __forceinline__ unsigned f2tf(float f) {
    unsigned u; asm("cvt.rna.tf32.f32 %0, %1;" : "=r"(u) : "f"(f)); return u;
}
__device__ __forceinline__ unsigned r2tf(unsigned x) {
    unsigned u; asm("cvt.rna.tf32.f32 %0, %1;" : "=r"(u) : "f"(__uint_as_float(x))); return u;
}

#define MMA_TF32(d, a, b0_, b1_) \
    asm volatile("mma.sync.aligned.m16n8k8.row.col.f32.tf32.tf32.f32 " \
        "{%0,%1,%2,%3},{%4,%5,%6,%7},{%8,%9},{%0,%1,%2,%3};" \
        : "+f"(d[0]), "+f"(d[1]), "+f"(d[2]), "+f"(d[3]) \
        : "r"(a[0]), "r"(a[1]), "r"(a[2]), "r"(a[3]), "r"(b0_), "r"(b1_))

// one 128-row tile stage: raw fp32 rows -> swizzled smem via cp.async
__device__ __forceinline__ void stage_load(unsigned* buf, const float4* __restrict__ srcb,
                                           int row0, int N, int tid) {
#pragma unroll
    for (int i = 0; i < 16; i++) {
        int idx = tid + i * 256;
        int row = idx >> 5, kq = idx & 31;
        int grow = row0 + row;
        unsigned daddr = (unsigned)__cvta_generic_to_shared(
            buf + row * 128 + ((kq * 4) ^ ((row & 7) * 4)));
        const float4* s = srcb + (size_t)(grow < N ? grow : 0) * 32 + kq;
        int sz = grow < N ? 16 : 0;
        asm volatile("cp.async.cg.shared.global [%0], [%1], 16, %2;"
                     :: "r"(daddr), "l"(s), "r"(sz));
    }
}

// MODE 0 (res): y = relu(x@Wr + br)          (writes g_y)
// MODE 1 (h):   y = relu(cdst*(agg@W) + b) + g_y, plus BN column sums
// Block: 256 thr = 8 warps = 2(m) x 4(n); warp tile m64 x n32; BM=128 tiles.
template <int MODE>
__global__ __launch_bounds__(256, 1) void k_gemm(
    const float4* __restrict__ A4, const float* __restrict__ Wb,
    const float* __restrict__ bias, int N, int numTiles)
{
    extern __shared__ unsigned smem_u[];
    unsigned* ws  = smem_u;           // 16384 words = 64KB
    unsigned* as0 = smem_u + 16384;   // 16384 words = 64KB (128 rows)
    unsigned* as1 = smem_u + 32768;

    const int tid  = threadIdx.x;
    const int lane = tid & 31;
    const int wid  = tid >> 5;
    const int mw   = wid >> 2;     // 0..1
    const int nw   = wid & 3;      // 0..3
    const int tig  = lane & 3;
    const int gid  = lane >> 2;
    const int swz  = gid * 4;

    // ---- one-time: fragment-major packed weights in tf32 ----
    for (int cell = tid; cell < 4096; cell += 256) {
        int j2  = cell & 7;
        int l   = (cell >> 3) & 31;
        int t   = (cell >> 8) & 3;
        int cnw = (cell >> 10) & 3;
        int n  = cnw * 32 + t * 8 + (l >> 2);
        int k0 = j2 * 16 + (l & 3);
        uint4 v;
        v.x = f2tf(__ldg(&Wb[(k0     ) * D + n]));
        v.y = f2tf(__ldg(&Wb[(k0 +  4) * D + n]));
        v.z = f2tf(__ldg(&Wb[(k0 +  8) * D + n]));
        v.w = f2tf(__ldg(&Wb[(k0 + 12) * D + n]));
        *(uint4*)(ws + (cnw * 4 + t) * 1024 + l * 32 + ((j2 ^ (l & 7)) << 2)) = v;
    }

    float b_[8];
#pragma unroll
    for (int t = 0; t < 4; t++) {
        int col = nw * 32 + t * 8 + 2 * tig;
        b_[2 * t] = __ldg(&bias[col]); b_[2 * t + 1] = __ldg(&bias[col + 1]);
    }

    float ts[8], tq[8];
    if (MODE == 1) {
#pragma unroll
        for (int i = 0; i < 8; i++) { ts[i] = 0.f; tq[i] = 0.f; }
    }

    const int nT = (numTiles > blockIdx.x)
                 ? (numTiles - blockIdx.x + gridDim.x - 1) / gridDim.x : 0;

    stage_load(as0, A4, blockIdx.x * BM, N, tid);
    asm volatile("cp.async.commit_group;");
    stage_load(as1, A4, (blockIdx.x + gridDim.x) * BM, N, tid);
    asm volatile("cp.async.commit_group;");

    for (int s = 0; s < nT; s++) {
        const int tile = blockIdx.x + s * gridDim.x;
        const int row0 = tile * BM;

        asm volatile("cp.async.wait_group 1;");
        __syncthreads();
        const unsigned* asb = (s & 1) ? as1 : as0;

        float acc[4][4][4];
#pragma unroll
        for (int mf = 0; mf < 4; mf++)
#pragma unroll
            for (int t = 0; t < 4; t++)
#pragma unroll
                for (int r = 0; r < 4; r++) acc[mf][t][r] = 0.f;

#pragma unroll
        for (int jp = 0; jp < 8; jp++) {
            unsigned a[4][2][4];
#pragma unroll
            for (int mf = 0; mf < 4; mf++) {
                const unsigned* base = asb + (mw * 64 + mf * 16 + gid) * 128;
#pragma unroll
                for (int dj = 0; dj < 2; dj++) {
                    int k0 = jp * 16 + dj * 8 + tig;
                    a[mf][dj][0] = r2tf(base[(k0) ^ swz]);
                    a[mf][dj][1] = r2tf(base[1024 + ((k0) ^ swz)]);
                    a[mf][dj][2] = r2tf(base[(k0 + 4) ^ swz]);
                    a[mf][dj][3] = r2tf(base[1024 + ((k0 + 4) ^ swz)]);
                }
            }
#pragma unroll
            for (int t = 0; t < 4; t++) {
                uint4 bf = *(const uint4*)(ws + (nw * 4 + t) * 1024 + lane * 32 +
                                           ((jp ^ (lane & 7)) << 2));
#pragma unroll
                for (int mf = 0; mf < 4; mf++) {
                    MMA_TF32(acc[mf][t], a[mf][0], bf.x, bf.y);
                    MMA_TF32(acc[mf][t], a[mf][1], bf.z, bf.w);
                }
            }
        }

        __syncthreads();  // all reads of asb done before reload
        if (s + 2 < nT)
            stage_load((s & 1) ? as1 : as0, A4,
                       (blockIdx.x + (s + 2) * gridDim.x) * BM, N, tid);
        asm volatile("cp.async.commit_group;");

        // ---- epilogue ----
#pragma unroll
        for (int mf = 0; mf < 4; mf++) {
            int rA = row0 + mw * 64 + mf * 16 + gid;
            int rB = rA + 8;
#pragma unroll
            for (int t = 0; t < 4; t++) {
                int col = nw * 32 + t * 8 + 2 * tig;
                if (MODE == 0) {
                    if (rA < N) {
                        float v0 = fmaxf(acc[mf][t][0] + b_[2 * t], 0.f);
                        float v1 = fmaxf(acc[mf][t][1] + b_[2 * t + 1], 0.f);
                        *(float2*)&g_y[(size_t)rA * D + col] = make_float2(v0, v1);
                    }
                    if (rB < N) {
                        float v2 = fmaxf(acc[mf][t][2] + b_[2 * t], 0.f);
                        float v3 = fmaxf(acc[mf][t][3] + b_[2 * t + 1], 0.f);
                        *(float2*)&g_y[(size_t)rB * D + col] = make_float2(v2, v3);
                    }
                } else {
                    if (rA < N) {
                        float cdA = __ldg(&g_cdst[rA]);
                        float2 pv = *(const float2*)&g_y[(size_t)rA * D + col];
                        float v0 = fmaxf(acc[mf][t][0] * cdA + b_[2 * t], 0.f) + pv.x;
                        float v1 = fmaxf(acc[mf][t][1] * cdA + b_[2 * t + 1], 0.f) + pv.y;
                        *(float2*)&g_y[(size_t)rA * D + col] = make_float2(v0, v1);
                        ts[2 * t] += v0; tq[2 * t] += v0 * v0;
                        ts[2 * t + 1] += v1; tq[2 * t + 1] += v1 * v1;
                    }
                    if (rB < N) {
                        float cdB = __ldg(&g_cdst[rB]);
                        float2 pv = *(const float2*)&g_y[(size_t)rB * D + col];
                        float v2 = fmaxf(acc[mf][t][2] * cdB + b_[2 * t], 0.f) + pv.x;
                        float v3 = fmaxf(acc[mf][t][3] * cdB + b_[2 * t + 1], 0.f) + pv.y;
                        *(float2*)&g_y[(size_t)rB * D + col] = make_float2(v2, v3);
                        ts[2 * t] += v2; tq[2 * t] += v2 * v2;
                        ts[2 * t + 1] += v3; tq[2 * t + 1] += v3 * v3;
                    }
                }
            }
        }
    }

    if (MODE == 1) {
#pragma unroll
        for (int i = 0; i < 8; i++) {
#pragma unroll
            for (int m = 4; m <= 16; m <<= 1) {
                ts[i] += __shfl_xor_sync(0xffffffffu, ts[i], m);
                tq[i] += __shfl_xor_sync(0xffffffffu, tq[i], m);
            }
        }
        if (gid == 0) {
#pragma unroll
            for (int i = 0; i < 8; i++) {
                int col = nw * 32 + (i >> 1) * 8 + 2 * tig + (i & 1);
                atomicAdd(&g_colsum[col], ts[i]);
                atomicAdd(&g_colsq[col], tq[i]);
            }
        }
    }
}

// ---------------- BN parameter fold + apply ----------------------------------
__global__ void k_bnparams(const float* __restrict__ gamma, const float* __restrict__ beta, float invN) {
    int j = threadIdx.x;
    float mean = g_colsum[j] * invN;
    float var = fmaxf(g_colsq[j] * invN - mean * mean, 0.f);
    float s = rsqrtf(var + BN_EPS) * __ldg(&gamma[j]);
    g_scale[j] = s;
    g_shift[j] = __ldg(&beta[j]) - mean * s;
}

__global__ __launch_bounds__(256) void k_bnapply(float4* __restrict__ out4, int total4) {
    int i = blockIdx.x * blockDim.x + threadIdx.x;
    if (i >= total4) return;
    const float4* y4 = (const float4*)g_y;
    const float4* s4 = (const float4*)g_scale;
    const float4* t4 = (const float4*)g_shift;
    int c = i & 31;
    float4 v = y4[i];
    float4 s = s4[c];
    float4 t = t4[c];
    out4[i] = make_float4(v.x * s.x + t.x, v.y * s.y + t.y,
                          v.z * s.z + t.z, v.w * s.w + t.w);
}

// ---------------- launch ------------------------------------------------------
extern "C" void kernel_launch(void* const* d_in, const int* in_sizes, int n_in,
                              void* d_out, int out_size) {
    const float* x     = (const float*)d_in[0];
    const float* W     = (const float*)d_in[1];
    const float* b     = (const float*)d_in[2];
    const float* Wr    = (const float*)d_in[3];
    const float* br    = (const float*)d_in[4];
    const float* gamma = (const float*)d_in[5];
    const float* beta  = (const float*)d_in[6];
    const int*   src   = (const int*)d_in[7];
    const int*   dst   = (const int*)d_in[8];

    const int N = in_sizes[0] / D;
    const int E = in_sizes[7];

    // one-time host resources for graph fork/join (host objects, no device mem)
    static cudaStream_t s_res = nullptr;
    static cudaEvent_t ev_fork = nullptr, ev_join = nullptr;
    static bool attrs_set = false;
    const int smemBytes = 49152 * (int)sizeof(unsigned);  // 192 KB
    if (!s_res) {
        cudaStreamCreateWithFlags(&s_res, cudaStreamNonBlocking);
        cudaEventCreateWithFlags(&ev_fork, cudaEventDisableTiming);
        cudaEventCreateWithFlags(&ev_join, cudaEventDisableTiming);
    }
    if (!attrs_set) {
        cudaFuncSetAttribute(k_gemm<0>, cudaFuncAttributeMaxDynamicSharedMemorySize, smemBytes);
        cudaFuncSetAttribute(k_gemm<1>, cudaFuncAttributeMaxDynamicSharedMemorySize, smemBytes);
        attrs_set = true;
    }

    // device addresses of __device__ symbols (host-side symbol address is NOT
    // a device pointer — this was the round-5 bug)
    void *p_agg, *p_odeg, *p_ideg, *p_colsum, *p_colsq;
    cudaGetSymbolAddress(&p_agg, g_agg);
    cudaGetSymbolAddress(&p_odeg, g_odeg);
    cudaGetSymbolAddress(&p_ideg, g_ideg);
    cudaGetSymbolAddress(&p_colsum, g_colsum);
    cudaGetSymbolAddress(&p_colsq, g_colsq);

    const int numTiles = (N + BM - 1) / BM;
    const int grid = numTiles < 152 ? numTiles : 152;

    // fork: residual GEMM (depends only on x) runs parallel to the agg chain
    cudaEventRecord(ev_fork, 0);
    cudaStreamWaitEvent(s_res, ev_fork, 0);
    k_gemm<0><<<grid, 256, smemBytes, s_res>>>((const float4*)x, Wr, br, N, numTiles);
    cudaEventRecord(ev_join, s_res);

    // main chain: memsets -> degrees -> cnorm -> aggregate
    cudaMemsetAsync(p_agg, 0, (size_t)N * D * sizeof(float));
    cudaMemsetAsync(p_odeg, 0, (size_t)N * sizeof(int));
    cudaMemsetAsync(p_ideg, 0, (size_t)N * sizeof(int));
    cudaMemsetAsync(p_colsum, 0, D * sizeof(float));
    cudaMemsetAsync(p_colsq, 0, D * sizeof(float));

    k_degrees<<<(E + 255) / 256, 256>>>(src, dst, E);
    k_cnorm<<<(N + 255) / 256, 256>>>(N);

    {
        long long threads = (long long)E * 32;
        int blocks = (int)((threads + 255) / 256);
        k_aggregate<<<blocks, 256>>>((const float4*)x, src, dst, E);
    }

    // join: h GEMM needs agg (main chain) + residual y (side stream)
    cudaStreamWaitEvent(0, ev_join, 0);
    k_gemm<1><<<grid, 256, smemBytes>>>((const float4*)p_agg, W, b, N, numTiles);

    k_bnparams<<<1, D>>>(gamma, beta, 1.0f / (float)N);
    {
        int total4 = N * (D / 4);
        k_bnapply<<<(total4 + 255) / 256, 256>>>((float4*)d_out, total4);
    }
}

// round 7
// speedup vs baseline: 1.3913x; 1.3913x over previous
#include <cuda_runtime.h>
#include <cstdint>

#define D 128
#define MAXN 100000
#define BM 64
#define BN_EPS 1e-5f
// compensation for tf32 RZ truncation of A operands (E[rel loss] ~ 3.5e-4)
#define TRUNC_COMP 1.00035f

// ---------------- scratch (device globals; no runtime allocation) -----------
__device__ __align__(16) float g_agg[(size_t)MAXN * D];
__device__ __align__(16) float g_y[(size_t)MAXN * D];
__device__ float g_csrc[MAXN];
__device__ float g_cdst[MAXN];
__device__ int   g_odeg[MAXN];
__device__ int   g_ideg[MAXN];
__device__ __align__(16) float g_colsum[D];
__device__ __align__(16) float g_colsq[D];
__device__ __align__(16) float g_scale[D];
__device__ __align__(16) float g_shift[D];

// ---------------- degree histograms -----------------------------------------
__global__ void k_degrees(const int* __restrict__ src, const int* __restrict__ dst, int E) {
    int e = blockIdx.x * blockDim.x + threadIdx.x;
    if (e < E) {
        atomicAdd(&g_odeg[src[e]], 1);
        atomicAdd(&g_ideg[dst[e]], 1);
    }
}

__global__ void k_cnorm(int N) {
    int i = blockIdx.x * blockDim.x + threadIdx.x;
    if (i < N) {
        g_csrc[i] = rsqrtf(fmaxf((float)g_odeg[i], 1.0f));
        g_cdst[i] = rsqrtf(fmaxf((float)g_ideg[i], 1.0f));
    }
}

// ---------------- edge aggregation: 4 edges per warp (8 lanes/edge) ----------
// lane l: edge = warp*4 + (l>>3), chunk c = l&7; 4 independent 16B chains/lane
__global__ __launch_bounds__(256) void k_aggregate(
    const float4* __restrict__ x4, const int* __restrict__ src,
    const int* __restrict__ dst, int E) {
    int t = blockIdx.x * blockDim.x + threadIdx.x;
    int e = (t >> 5) * 4 + ((t & 31) >> 3);
    if (e >= E) return;
    int c = t & 7;
    int s = __ldg(&src[e]);
    int d = __ldg(&dst[e]);
    float cs = __ldg(&g_csrc[s]);
    const float4* xb = x4 + (size_t)s * 32;
    float4 v0 = __ldg(xb + c);
    float4 v1 = __ldg(xb + c + 8);
    float4 v2 = __ldg(xb + c + 16);
    float4 v3 = __ldg(xb + c + 24);
    float* p = g_agg + (size_t)d * D;
#define RED4(vv, off)                                                          \
    asm volatile("red.global.add.v4.f32 [%0], {%1, %2, %3, %4};"               \
                 :: "l"(p + (off) * 4), "f"((vv).x * cs), "f"((vv).y * cs),    \
                    "f"((vv).z * cs), "f"((vv).w * cs) : "memory")
    RED4(v0, c);
    RED4(v1, c + 8);
    RED4(v2, c + 16);
    RED4(v3, c + 24);
#undef RED4
}

// ---------------- tf32 tensor-core fused dual GEMM ---------------------------
__device__ __forceinline__ unsigned f2tf(float f) {
    unsigned u; asm("cvt.rna.tf32.f32 %0, %1;" : "=r"(u) : "f"(f)); return u;
}

#define MMA_TF32(d, a, b0_, b1_) \
    asm volatile("mma.sync.aligned.m16n8k8.row.col.f32.tf32.tf32.f32 " \
        "{%0,%1,%2,%3},{%4,%5,%6,%7},{%8,%9},{%0,%1,%2,%3};" \
        : "+f"(d[0]), "+f"(d[1]), "+f"(d[2]), "+f"(d[3]) \
        : "r"(a[0]), "r"(a[1]), "r"(a[2]), "r"(a[3]), "r"(b0_), "r"(b1_))

// issue one (tile,branch) stage: raw fp32 rows -> swizzled smem via cp.async
__device__ __forceinline__ void stage_load(unsigned* buf, const float4* __restrict__ srcb,
                                           int row0, int N, int tid) {
#pragma unroll
    for (int i = 0; i < 8; i++) {
        int idx = tid + i * 256;
        int row = idx >> 5, kq = idx & 31;
        int grow = row0 + row;
        unsigned daddr = (unsigned)__cvta_generic_to_shared(
            buf + row * 128 + ((kq * 4) ^ ((row & 7) * 4)));
        const float4* s = srcb + (size_t)(grow < N ? grow : 0) * 32 + kq;
        int sz = grow < N ? 16 : 0;
        asm volatile("cp.async.cg.shared.global [%0], [%1], 16, %2;"
                     :: "r"(daddr), "l"(s), "r"(sz));
    }
}

// jp-loop for one branch; A operands are RAW fp32 bits (MMA truncates to tf32;
// bias compensated via TRUNC_COMP folded into the weights)
#define MMA_STAGE(ACC, BR)                                                         \
    _Pragma("unroll")                                                              \
    for (int jp = 0; jp < 8; jp++) {                                               \
        unsigned a[2][2][4];                                                       \
        _Pragma("unroll")                                                          \
        for (int mf = 0; mf < 2; mf++) {                                           \
            const unsigned* base = asb + (mw * 32 + mf * 16 + gid) * 128;          \
            _Pragma("unroll")                                                      \
            for (int dj = 0; dj < 2; dj++) {                                       \
                int k0 = jp * 16 + dj * 8 + tig;                                   \
                a[mf][dj][0] = base[(k0) ^ swz];                                   \
                a[mf][dj][1] = base[1024 + ((k0) ^ swz)];                          \
                a[mf][dj][2] = base[(k0 + 4) ^ swz];                               \
                a[mf][dj][3] = base[1024 + ((k0 + 4) ^ swz)];                      \
            }                                                                      \
        }                                                                          \
        _Pragma("unroll")                                                          \
        for (int t = 0; t < 4; t++) {                                              \
            int region = (nw * 2 + (BR)) * 4 + t;                                  \
            uint4 bf = *(const uint4*)(ws + region * 1024 + lane * 32 +            \
                                       ((jp ^ (lane & 7)) << 2));                  \
            _Pragma("unroll")                                                      \
            for (int mf = 0; mf < 2; mf++) {                                       \
                MMA_TF32(ACC[mf][t], a[mf][0], bf.x, bf.y);                        \
                MMA_TF32(ACC[mf][t], a[mf][1], bf.z, bf.w);                        \
            }                                                                      \
        }                                                                          \
    }

// Block: 256 thr = 8 warps = 2(m) x 4(n); warp tile m32 x n32, both branches.
// smem: ws = fragment-major tf32 W/Wr (128KB), as0/as1 = 32KB A stages.
__global__ __launch_bounds__(256, 1) void k_gemm_tf32(
    const float4* __restrict__ x4, const float* __restrict__ W,
    const float* __restrict__ bb, const float* __restrict__ Wr,
    const float* __restrict__ brr, int N, int numTiles)
{
    extern __shared__ unsigned smem_u[];
    unsigned* ws  = smem_u;           // 32768 words = 128KB
    unsigned* as0 = smem_u + 32768;   //  8192 words =  32KB
    unsigned* as1 = smem_u + 40960;   //  8192 words =  32KB

    const int tid  = threadIdx.x;
    const int lane = tid & 31;
    const int wid  = tid >> 5;
    const int mw   = wid >> 2;     // 0..1
    const int nw   = wid & 3;      // 0..3
    const int tig  = lane & 3;
    const int gid  = lane >> 2;
    const int swz  = gid * 4;

    const float4* agg4 = (const float4*)g_agg;

    // ---- one-time: fragment-major packed W/Wr in tf32 (RNA, bias-compensated)
    for (int cell = tid; cell < 8192; cell += 256) {
        int j2  = cell & 7;
        int l   = (cell >> 3) & 31;
        int t   = (cell >> 8) & 3;
        int cbr = (cell >> 10) & 1;
        int cnw = (cell >> 11) & 3;
        const float* Wb = cbr ? Wr : W;
        int n  = cnw * 32 + t * 8 + (l >> 2);
        int k0 = j2 * 16 + (l & 3);
        uint4 v;
        v.x = f2tf(__ldg(&Wb[(k0     ) * D + n]) * TRUNC_COMP);
        v.y = f2tf(__ldg(&Wb[(k0 +  4) * D + n]) * TRUNC_COMP);
        v.z = f2tf(__ldg(&Wb[(k0 +  8) * D + n]) * TRUNC_COMP);
        v.w = f2tf(__ldg(&Wb[(k0 + 12) * D + n]) * TRUNC_COMP);
        int region = (cnw * 2 + cbr) * 4 + t;
        *(uint4*)(ws + region * 1024 + l * 32 + ((j2 ^ (l & 7)) << 2)) = v;
    }

    // biases for this thread's 8 output columns
    float b_[8], q_[8];
#pragma unroll
    for (int t = 0; t < 4; t++) {
        int col = nw * 32 + t * 8 + 2 * tig;
        b_[2 * t] = __ldg(&bb[col]);   b_[2 * t + 1] = __ldg(&bb[col + 1]);
        q_[2 * t] = __ldg(&brr[col]);  q_[2 * t + 1] = __ldg(&brr[col + 1]);
    }

    float ts[8], tq[8];
#pragma unroll
    for (int i = 0; i < 8; i++) { ts[i] = 0.f; tq[i] = 0.f; }

    const int nT = (numTiles - blockIdx.x + gridDim.x - 1) / gridDim.x;
    const int totalS = nT * 2;

    // prologue: stages 0 (agg of tile0) and 1 (x of tile0)
    stage_load(as0, agg4, blockIdx.x * BM, N, tid);
    asm volatile("cp.async.commit_group;");
    stage_load(as1, x4, blockIdx.x * BM, N, tid);
    asm volatile("cp.async.commit_group;");

    float acc0[2][4][4], acc1[2][4][4];

    for (int s = 0; s < totalS; s++) {
        const int br   = s & 1;
        const int tile = blockIdx.x + (s >> 1) * gridDim.x;
        const int row0 = tile * BM;

        asm volatile("cp.async.wait_group 1;");
        __syncthreads();
        const unsigned* asb = br ? as1 : as0;

        if (br == 0) {
#pragma unroll
            for (int mf = 0; mf < 2; mf++)
#pragma unroll
                for (int t = 0; t < 4; t++)
#pragma unroll
                    for (int r = 0; r < 4; r++) { acc0[mf][t][r] = 0.f; acc1[mf][t][r] = 0.f; }
            MMA_STAGE(acc0, 0)
        } else {
            MMA_STAGE(acc1, 1)
        }

        __syncthreads();  // all reads of asb done before overwrite

        int s2 = s + 2;
        if (s2 < totalS) {
            int t2 = blockIdx.x + (s2 >> 1) * gridDim.x;
            stage_load((s2 & 1) ? as1 : as0, (s2 & 1) ? x4 : agg4, t2 * BM, N, tid);
        }
        asm volatile("cp.async.commit_group;");

        if (br == 1) {
            // epilogue: h*c_dst + b -> relu, + relu(res+br), write y, BN sums
#pragma unroll
            for (int mf = 0; mf < 2; mf++) {
                int rA = row0 + mw * 32 + mf * 16 + gid;
                int rB = rA + 8;
                float cdA = (rA < N) ? __ldg(&g_cdst[rA]) : 0.f;
                float cdB = (rB < N) ? __ldg(&g_cdst[rB]) : 0.f;
#pragma unroll
                for (int t = 0; t < 4; t++) {
                    int col = nw * 32 + t * 8 + 2 * tig;
                    if (rA < N) {
                        float v0 = fmaxf(acc0[mf][t][0] * cdA + b_[2 * t], 0.f)
                                 + fmaxf(acc1[mf][t][0] + q_[2 * t], 0.f);
                        float v1 = fmaxf(acc0[mf][t][1] * cdA + b_[2 * t + 1], 0.f)
                                 + fmaxf(acc1[mf][t][1] + q_[2 * t + 1], 0.f);
                        *(float2*)&g_y[(size_t)rA * D + col] = make_float2(v0, v1);
                        ts[2 * t] += v0; tq[2 * t] += v0 * v0;
                        ts[2 * t + 1] += v1; tq[2 * t + 1] += v1 * v1;
                    }
                    if (rB < N) {
                        float v2 = fmaxf(acc0[mf][t][2] * cdB + b_[2 * t], 0.f)
                                 + fmaxf(acc1[mf][t][2] + q_[2 * t], 0.f);
                        float v3 = fmaxf(acc0[mf][t][3] * cdB + b_[2 * t + 1], 0.f)
                                 + fmaxf(acc1[mf][t][3] + q_[2 * t + 1], 0.f);
                        *(float2*)&g_y[(size_t)rB * D + col] = make_float2(v2, v3);
                        ts[2 * t] += v2; tq[2 * t] += v2 * v2;
                        ts[2 * t + 1] += v3; tq[2 * t + 1] += v3 * v3;
                    }
                }
            }
        }
    }

    // ---- BN sums: lanes gid 0..7 hold identical column sets -> reduce ----
#pragma unroll
    for (int i = 0; i < 8; i++) {
#pragma unroll
        for (int m = 4; m <= 16; m <<= 1) {
            ts[i] += __shfl_xor_sync(0xffffffffu, ts[i], m);
            tq[i] += __shfl_xor_sync(0xffffffffu, tq[i], m);
        }
    }
    if (gid == 0) {
#pragma unroll
        for (int i = 0; i < 8; i++) {
            int col = nw * 32 + (i >> 1) * 8 + 2 * tig + (i & 1);
            atomicAdd(&g_colsum[col], ts[i]);
            atomicAdd(&g_colsq[col], tq[i]);
        }
    }
}

// ---------------- BN parameter fold + apply ----------------------------------
__global__ void k_bnparams(const float* __restrict__ gamma, const float* __restrict__ beta, float invN) {
    int j = threadIdx.x;
    float mean = g_colsum[j] * invN;
    float var = fmaxf(g_colsq[j] * invN - mean * mean, 0.f);
    float s = rsqrtf(var + BN_EPS) * __ldg(&gamma[j]);
    g_scale[j] = s;
    g_shift[j] = __ldg(&beta[j]) - mean * s;
}

__global__ __launch_bounds__(256) void k_bnapply(float4* __restrict__ out4, int total4) {
    int i = blockIdx.x * blockDim.x + threadIdx.x;
    if (i >= total4) return;
    const float4* y4 = (const float4*)g_y;
    const float4* s4 = (const float4*)g_scale;
    const float4* t4 = (const float4*)g_shift;
    int c = i & 31;
    float4 v = y4[i];
    float4 s = s4[c];
    float4 t = t4[c];
    out4[i] = make_float4(v.x * s.x + t.x, v.y * s.y + t.y,
                          v.z * s.z + t.z, v.w * s.w + t.w);
}

// ---------------- launch ------------------------------------------------------
extern "C" void kernel_launch(void* const* d_in, const int* in_sizes, int n_in,
                              void* d_out, int out_size) {
    const float* x     = (const float*)d_in[0];
    const float* W     = (const float*)d_in[1];
    const float* b     = (const float*)d_in[2];
    const float* Wr    = (const float*)d_in[3];
    const float* br    = (const float*)d_in[4];
    const float* gamma = (const float*)d_in[5];
    const float* beta  = (const float*)d_in[6];
    const int*   src   = (const int*)d_in[7];
    const int*   dst   = (const int*)d_in[8];

    const int N = in_sizes[0] / D;
    const int E = in_sizes[7];

    void *p_agg, *p_odeg, *p_ideg, *p_colsum, *p_colsq;
    cudaGetSymbolAddress(&p_agg, g_agg);
    cudaGetSymbolAddress(&p_odeg, g_odeg);
    cudaGetSymbolAddress(&p_ideg, g_ideg);
    cudaGetSymbolAddress(&p_colsum, g_colsum);
    cudaGetSymbolAddress(&p_colsq, g_colsq);

    cudaMemsetAsync(p_agg, 0, (size_t)N * D * sizeof(float));
    cudaMemsetAsync(p_odeg, 0, (size_t)N * sizeof(int));
    cudaMemsetAsync(p_ideg, 0, (size_t)N * sizeof(int));
    cudaMemsetAsync(p_colsum, 0, D * sizeof(float));
    cudaMemsetAsync(p_colsq, 0, D * sizeof(float));

    k_degrees<<<(E + 255) / 256, 256>>>(src, dst, E);
    k_cnorm<<<(N + 255) / 256, 256>>>(N);

    {
        // 4 edges per warp -> 32 edges per 256-thread block
        int blocks = (E + 31) / 32;
        k_aggregate<<<blocks, 256>>>((const float4*)x, src, dst, E);
    }

    {
        const int smemBytes = 49152 * (int)sizeof(unsigned);  // 192 KB
        cudaFuncSetAttribute(k_gemm_tf32, cudaFuncAttributeMaxDynamicSharedMemorySize, smemBytes);
        int numTiles = (N + BM - 1) / BM;
        int grid = numTiles < 152 ? numTiles : 152;
        k_gemm_tf32<<<grid, 256, smemBytes>>>(
            (const float4*)x, W, b, Wr, br, N, numTiles);
    }

    k_bnparams<<<1, D>>>(gamma, beta, 1.0f / (float)N);
    {
        int total4 = N * (D / 4);
        k_bnapply<<<(total4 + 255) / 256, 256>>>((float4*)d_out, total4);
    }
}

// round 8
// speedup vs baseline: 1.3972x; 1.0042x over previous
#include <cuda_runtime.h>
#include <cstdint>

#define D 128
#define MAXN 100000
#define BM 64
#define BN_EPS 1e-5f
// compensation for tf32 RZ truncation of A operands (E[rel loss] ~ 3.5e-4)
#define TRUNC_COMP 1.00035f

// ---------------- scratch (device globals; no runtime allocation) -----------
__device__ __align__(16) float g_agg[(size_t)MAXN * D];
__device__ __align__(16) float g_y[(size_t)MAXN * D];
__device__ float g_csrc[MAXN];
__device__ float g_cdst[MAXN];
__device__ int   g_odeg[MAXN];
__device__ int   g_ideg[MAXN];
__device__ __align__(16) float g_colsum[D];
__device__ __align__(16) float g_colsq[D];
__device__ __align__(16) float g_scale[D];
__device__ __align__(16) float g_shift[D];

// ---------------- degree histograms -----------------------------------------
__global__ void k_degrees(const int* __restrict__ src, const int* __restrict__ dst, int E) {
    int e = blockIdx.x * blockDim.x + threadIdx.x;
    if (e < E) {
        atomicAdd(&g_odeg[src[e]], 1);
        atomicAdd(&g_ideg[dst[e]], 1);
    }
}

__global__ void k_cnorm(int N) {
    int i = blockIdx.x * blockDim.x + threadIdx.x;
    if (i < N) {
        g_csrc[i] = rsqrtf(fmaxf((float)g_odeg[i], 1.0f));
        g_cdst[i] = rsqrtf(fmaxf((float)g_ideg[i], 1.0f));
    }
}

// ---------------- edge aggregation: 4 edges per warp (8 lanes/edge) ----------
// lane l: edge = warp*4 + (l>>3), chunk c = l&7; 4 independent 16B chains/lane
__global__ __launch_bounds__(256) void k_aggregate(
    const float4* __restrict__ x4, const int* __restrict__ src,
    const int* __restrict__ dst, int E) {
    int t = blockIdx.x * blockDim.x + threadIdx.x;
    int e = (t >> 5) * 4 + ((t & 31) >> 3);
    if (e >= E) return;
    int c = t & 7;
    int s = __ldg(&src[e]);
    int d = __ldg(&dst[e]);
    float cs = __ldg(&g_csrc[s]);
    const float4* xb = x4 + (size_t)s * 32;
    float4 v0 = __ldg(xb + c);
    float4 v1 = __ldg(xb + c + 8);
    float4 v2 = __ldg(xb + c + 16);
    float4 v3 = __ldg(xb + c + 24);
    float* p = g_agg + (size_t)d * D;
#define RED4(vv, off)                                                          \
    asm volatile("red.global.add.v4.f32 [%0], {%1, %2, %3, %4};"               \
                 :: "l"(p + (off) * 4), "f"((vv).x * cs), "f"((vv).y * cs),    \
                    "f"((vv).z * cs), "f"((vv).w * cs) : "memory")
    RED4(v0, c);
    RED4(v1, c + 8);
    RED4(v2, c + 16);
    RED4(v3, c + 24);
#undef RED4
}

// ---------------- tf32 tensor-core fused dual GEMM ---------------------------
__device__ __forceinline__ unsigned f2tf(float f) {
    unsigned u; asm("cvt.rna.tf32.f32 %0, %1;" : "=r"(u) : "f"(f)); return u;
}

#define MMA_TF32(d, a, b0_, b1_) \
    asm volatile("mma.sync.aligned.m16n8k8.row.col.f32.tf32.tf32.f32 " \
        "{%0,%1,%2,%3},{%4,%5,%6,%7},{%8,%9},{%0,%1,%2,%3};" \
        : "+f"(d[0]), "+f"(d[1]), "+f"(d[2]), "+f"(d[3]) \
        : "r"(a[0]), "r"(a[1]), "r"(a[2]), "r"(a[3]), "r"(b0_), "r"(b1_))

// issue one (tile,branch) stage: raw fp32 rows -> swizzled smem via cp.async
__device__ __forceinline__ void stage_load(unsigned* buf, const float4* __restrict__ srcb,
                                           int row0, int N, int tid) {
#pragma unroll
    for (int i = 0; i < 8; i++) {
        int idx = tid + i * 256;
        int row = idx >> 5, kq = idx & 31;
        int grow = row0 + row;
        unsigned daddr = (unsigned)__cvta_generic_to_shared(
            buf + row * 128 + ((kq * 4) ^ ((row & 7) * 4)));
        const float4* s = srcb + (size_t)(grow < N ? grow : 0) * 32 + kq;
        int sz = grow < N ? 16 : 0;
        asm volatile("cp.async.cg.shared.global [%0], [%1], 16, %2;"
                     :: "r"(daddr), "l"(s), "r"(sz));
    }
}

// jp-loop for one branch; A operands are RAW fp32 bits (MMA truncates to tf32;
// bias compensated via TRUNC_COMP folded into the weights)
#define MMA_STAGE(ACC, BR)                                                         \
    _Pragma("unroll")                                                              \
    for (int jp = 0; jp < 8; jp++) {                                               \
        unsigned a[2][2][4];                                                       \
        _Pragma("unroll")                                                          \
        for (int mf = 0; mf < 2; mf++) {                                           \
            const unsigned* base = asb + (mw * 32 + mf * 16 + gid) * 128;          \
            _Pragma("unroll")                                                      \
            for (int dj = 0; dj < 2; dj++) {                                       \
                int k0 = jp * 16 + dj * 8 + tig;                                   \
                a[mf][dj][0] = base[(k0) ^ swz];                                   \
                a[mf][dj][1] = base[1024 + ((k0) ^ swz)];                          \
                a[mf][dj][2] = base[(k0 + 4) ^ swz];                               \
                a[mf][dj][3] = base[1024 + ((k0 + 4) ^ swz)];                      \
            }                                                                      \
        }                                                                          \
        _Pragma("unroll")                                                          \
        for (int t = 0; t < 4; t++) {                                              \
            int region = (nw * 2 + (BR)) * 4 + t;                                  \
            uint4 bf = *(const uint4*)(ws + region * 1024 + lane * 32 +            \
                                       ((jp ^ (lane & 7)) << 2));                  \
            _Pragma("unroll")                                                      \
            for (int mf = 0; mf < 2; mf++) {                                       \
                MMA_TF32(ACC[mf][t], a[mf][0], bf.x, bf.y);                        \
                MMA_TF32(ACC[mf][t], a[mf][1], bf.z, bf.w);                        \
            }                                                                      \
        }                                                                          \
    }

// Block: 256 thr = 8 warps = 2(m) x 4(n); warp tile m32 x n32, both branches.
// smem: ws = fragment-major tf32 W/Wr (128KB), as0/as1 = 32KB A stages.
__global__ __launch_bounds__(256, 1) void k_gemm_tf32(
    const float4* __restrict__ x4, const float* __restrict__ W,
    const float* __restrict__ bb, const float* __restrict__ Wr,
    const float* __restrict__ brr, int N, int numTiles)
{
    extern __shared__ unsigned smem_u[];
    unsigned* ws  = smem_u;           // 32768 words = 128KB
    unsigned* as0 = smem_u + 32768;   //  8192 words =  32KB
    unsigned* as1 = smem_u + 40960;   //  8192 words =  32KB

    const int tid  = threadIdx.x;
    const int lane = tid & 31;
    const int wid  = tid >> 5;
    const int mw   = wid >> 2;     // 0..1
    const int nw   = wid & 3;      // 0..3
    const int tig  = lane & 3;
    const int gid  = lane >> 2;
    const int swz  = gid * 4;

    const float4* agg4 = (const float4*)g_agg;

    // ---- one-time: fragment-major packed W/Wr in tf32 (RNA, bias-compensated)
    for (int cell = tid; cell < 8192; cell += 256) {
        int j2  = cell & 7;
        int l   = (cell >> 3) & 31;
        int t   = (cell >> 8) & 3;
        int cbr = (cell >> 10) & 1;
        int cnw = (cell >> 11) & 3;
        const float* Wb = cbr ? Wr : W;
        int n  = cnw * 32 + t * 8 + (l >> 2);
        int k0 = j2 * 16 + (l & 3);
        uint4 v;
        v.x = f2tf(__ldg(&Wb[(k0     ) * D + n]) * TRUNC_COMP);
        v.y = f2tf(__ldg(&Wb[(k0 +  4) * D + n]) * TRUNC_COMP);
        v.z = f2tf(__ldg(&Wb[(k0 +  8) * D + n]) * TRUNC_COMP);
        v.w = f2tf(__ldg(&Wb[(k0 + 12) * D + n]) * TRUNC_COMP);
        int region = (cnw * 2 + cbr) * 4 + t;
        *(uint4*)(ws + region * 1024 + l * 32 + ((j2 ^ (l & 7)) << 2)) = v;
    }

    // biases for this thread's 8 output columns
    float b_[8], q_[8];
#pragma unroll
    for (int t = 0; t < 4; t++) {
        int col = nw * 32 + t * 8 + 2 * tig;
        b_[2 * t] = __ldg(&bb[col]);   b_[2 * t + 1] = __ldg(&bb[col + 1]);
        q_[2 * t] = __ldg(&brr[col]);  q_[2 * t + 1] = __ldg(&brr[col + 1]);
    }

    float ts[8], tq[8];
#pragma unroll
    for (int i = 0; i < 8; i++) { ts[i] = 0.f; tq[i] = 0.f; }

    const int nT = (numTiles - blockIdx.x + gridDim.x - 1) / gridDim.x;
    const int totalS = nT * 2;

    // prologue: stages 0 (agg of tile0) and 1 (x of tile0)
    stage_load(as0, agg4, blockIdx.x * BM, N, tid);
    asm volatile("cp.async.commit_group;");
    stage_load(as1, x4, blockIdx.x * BM, N, tid);
    asm volatile("cp.async.commit_group;");

    float acc0[2][4][4], acc1[2][4][4];

    for (int s = 0; s < totalS; s++) {
        const int br   = s & 1;
        const int tile = blockIdx.x + (s >> 1) * gridDim.x;
        const int row0 = tile * BM;

        asm volatile("cp.async.wait_group 1;");
        __syncthreads();
        const unsigned* asb = br ? as1 : as0;

        if (br == 0) {
#pragma unroll
            for (int mf = 0; mf < 2; mf++)
#pragma unroll
                for (int t = 0; t < 4; t++)
#pragma unroll
                    for (int r = 0; r < 4; r++) { acc0[mf][t][r] = 0.f; acc1[mf][t][r] = 0.f; }
            MMA_STAGE(acc0, 0)
        } else {
            MMA_STAGE(acc1, 1)
        }

        __syncthreads();  // all reads of asb done before overwrite

        int s2 = s + 2;
        if (s2 < totalS) {
            int t2 = blockIdx.x + (s2 >> 1) * gridDim.x;
            stage_load((s2 & 1) ? as1 : as0, (s2 & 1) ? x4 : agg4, t2 * BM, N, tid);
        }
        asm volatile("cp.async.commit_group;");

        if (br == 1) {
            // epilogue: h*c_dst + b -> relu, + relu(res+br), write y, BN sums
#pragma unroll
            for (int mf = 0; mf < 2; mf++) {
                int rA = row0 + mw * 32 + mf * 16 + gid;
                int rB = rA + 8;
                float cdA = (rA < N) ? __ldg(&g_cdst[rA]) : 0.f;
                float cdB = (rB < N) ? __ldg(&g_cdst[rB]) : 0.f;
#pragma unroll
                for (int t = 0; t < 4; t++) {
                    int col = nw * 32 + t * 8 + 2 * tig;
                    if (rA < N) {
                        float v0 = fmaxf(acc0[mf][t][0] * cdA + b_[2 * t], 0.f)
                                 + fmaxf(acc1[mf][t][0] + q_[2 * t], 0.f);
                        float v1 = fmaxf(acc0[mf][t][1] * cdA + b_[2 * t + 1], 0.f)
                                 + fmaxf(acc1[mf][t][1] + q_[2 * t + 1], 0.f);
                        *(float2*)&g_y[(size_t)rA * D + col] = make_float2(v0, v1);
                        ts[2 * t] += v0; tq[2 * t] += v0 * v0;
                        ts[2 * t + 1] += v1; tq[2 * t + 1] += v1 * v1;
                    }
                    if (rB < N) {
                        float v2 = fmaxf(acc0[mf][t][2] * cdB + b_[2 * t], 0.f)
                                 + fmaxf(acc1[mf][t][2] + q_[2 * t], 0.f);
                        float v3 = fmaxf(acc0[mf][t][3] * cdB + b_[2 * t + 1], 0.f)
                                 + fmaxf(acc1[mf][t][3] + q_[2 * t + 1], 0.f);
                        *(float2*)&g_y[(size_t)rB * D + col] = make_float2(v2, v3);
                        ts[2 * t] += v2; tq[2 * t] += v2 * v2;
                        ts[2 * t + 1] += v3; tq[2 * t + 1] += v3 * v3;
                    }
                }
            }
        }
    }

    // ---- BN sums: lanes gid 0..7 hold identical column sets -> reduce ----
#pragma unroll
    for (int i = 0; i < 8; i++) {
#pragma unroll
        for (int m = 4; m <= 16; m <<= 1) {
            ts[i] += __shfl_xor_sync(0xffffffffu, ts[i], m);
            tq[i] += __shfl_xor_sync(0xffffffffu, tq[i], m);
        }
    }
    if (gid == 0) {
#pragma unroll
        for (int i = 0; i < 8; i++) {
            int col = nw * 32 + (i >> 1) * 8 + 2 * tig + (i & 1);
            atomicAdd(&g_colsum[col], ts[i]);
            atomicAdd(&g_colsq[col], tq[i]);
        }
    }
}

// ---------------- BN parameter fold + apply ----------------------------------
__global__ void k_bnparams(const float* __restrict__ gamma, const float* __restrict__ beta, float invN) {
    int j = threadIdx.x;
    float mean = g_colsum[j] * invN;
    float var = fmaxf(g_colsq[j] * invN - mean * mean, 0.f);
    float s = rsqrtf(var + BN_EPS) * __ldg(&gamma[j]);
    g_scale[j] = s;
    g_shift[j] = __ldg(&beta[j]) - mean * s;
}

__global__ __launch_bounds__(256) void k_bnapply(float4* __restrict__ out4, int total4) {
    int i = blockIdx.x * blockDim.x + threadIdx.x;
    if (i >= total4) return;
    const float4* y4 = (const float4*)g_y;
    const float4* s4 = (const float4*)g_scale;
    const float4* t4 = (const float4*)g_shift;
    int c = i & 31;
    float4 v = y4[i];
    float4 s = s4[c];
    float4 t = t4[c];
    out4[i] = make_float4(v.x * s.x + t.x, v.y * s.y + t.y,
                          v.z * s.z + t.z, v.w * s.w + t.w);
}

// ---------------- launch ------------------------------------------------------
extern "C" void kernel_launch(void* const* d_in, const int* in_sizes, int n_in,
                              void* d_out, int out_size) {
    const float* x     = (const float*)d_in[0];
    const float* W     = (const float*)d_in[1];
    const float* b     = (const float*)d_in[2];
    const float* Wr    = (const float*)d_in[3];
    const float* br    = (const float*)d_in[4];
    const float* gamma = (const float*)d_in[5];
    const float* beta  = (const float*)d_in[6];
    const int*   src   = (const int*)d_in[7];
    const int*   dst   = (const int*)d_in[8];

    const int N = in_sizes[0] / D;
    const int E = in_sizes[7];

    void *p_agg, *p_odeg, *p_ideg, *p_colsum, *p_colsq;
    cudaGetSymbolAddress(&p_agg, g_agg);
    cudaGetSymbolAddress(&p_odeg, g_odeg);
    cudaGetSymbolAddress(&p_ideg, g_ideg);
    cudaGetSymbolAddress(&p_colsum, g_colsum);
    cudaGetSymbolAddress(&p_colsq, g_colsq);

    cudaMemsetAsync(p_agg, 0, (size_t)N * D * sizeof(float));
    cudaMemsetAsync(p_odeg, 0, (size_t)N * sizeof(int));
    cudaMemsetAsync(p_ideg, 0, (size_t)N * sizeof(int));
    cudaMemsetAsync(p_colsum, 0, D * sizeof(float));
    cudaMemsetAsync(p_colsq, 0, D * sizeof(float));

    k_degrees<<<(E + 255) / 256, 256>>>(src, dst, E);
    k_cnorm<<<(N + 255) / 256, 256>>>(N);

    {
        // 4 edges per warp -> 32 edges per 256-thread block
        int blocks = (E + 31) / 32;
        k_aggregate<<<blocks, 256>>>((const float4*)x, src, dst, E);
    }

    {
        const int smemBytes = 49152 * (int)sizeof(unsigned);  // 192 KB
        cudaFuncSetAttribute(k_gemm_tf32, cudaFuncAttributeMaxDynamicSharedMemorySize, smemBytes);
        int numTiles = (N + BM - 1) / BM;
        int grid = numTiles < 152 ? numTiles : 152;
        k_gemm_tf32<<<grid, 256, smemBytes>>>(
            (const float4*)x, W, b, Wr, br, N, numTiles);
    }

    k_bnparams<<<1, D>>>(gamma, beta, 1.0f / (float)N);
    {
        int total4 = N * (D / 4);
        k_bnapply<<<(total4 + 255) / 256, 256>>>((float4*)d_out, total4);
    }
}